// round 1
// baseline (speedup 1.0000x reference)
#include <cuda_runtime.h>
#include <math.h>
#include <stdint.h>

#define NN   50000
#define NE   800000
#define D_IN 128
#define D_HID 256
#define D_OUT 128
#define NL   8

// ------------------------- static device scratch -------------------------
__device__ float  g_dis[NN];            // deg -> deg^{-1/2}
__device__ int    g_rowptr[NN + 1];     // CSR (by destination) row pointers
__device__ int    g_cnt[NN];            // histogram, then scatter cursor
__device__ int    g_src[NE];            // CSR source node per slot
__device__ float  g_w[NE];              // CSR edge weight per slot
__device__ float  g_x0[(size_t)NN * D_HID];
__device__ float  g_t [(size_t)NN * D_HID];
__device__ float  g_h [(size_t)NN * D_HID];
__device__ double g_acc[2];             // sum, sumsq for graph layernorm
__device__ float  g_stats[2];           // mu, inv

// ------------------------- setup kernels -------------------------
__global__ void k_init() {
    int i = blockIdx.x * blockDim.x + threadIdx.x;
    if (i < NN) { g_dis[i] = 1.0f; g_cnt[i] = 0; }   // deg starts at 1 (self loop)
}

__global__ void k_edge_count(const int* __restrict__ ei) {
    int e = blockIdx.x * blockDim.x + threadIdx.x;
    if (e < NE) {
        int c = ei[NE + e];
        atomicAdd(&g_dis[c], 1.0f);
        atomicAdd(&g_cnt[c], 1);
    }
}

__global__ void k_rsqrt() {
    int i = blockIdx.x * blockDim.x + threadIdx.x;
    if (i < NN) g_dis[i] = rsqrtf(g_dis[i]);
}

// single-block exclusive scan of g_cnt -> g_rowptr (50001 entries)
__global__ void k_scan() {
    __shared__ int sh[1024];
    __shared__ int s_base;
    int tid = threadIdx.x;
    if (tid == 0) s_base = 0;
    __syncthreads();
    for (int base = 0; base < NN; base += 1024) {
        int i = base + tid;
        int v = (i < NN) ? g_cnt[i] : 0;
        sh[tid] = v;
        __syncthreads();
        for (int off = 1; off < 1024; off <<= 1) {
            int t = 0;
            if (tid >= off) t = sh[tid - off];
            __syncthreads();
            sh[tid] += t;
            __syncthreads();
        }
        if (i < NN) g_rowptr[i] = s_base + sh[tid] - v;  // exclusive
        __syncthreads();
        if (tid == 0) s_base += sh[1023];
        __syncthreads();
    }
    if (tid == 0) g_rowptr[NN] = s_base;
}

__global__ void k_cursor() {
    int i = blockIdx.x * blockDim.x + threadIdx.x;
    if (i < NN) g_cnt[i] = g_rowptr[i];
}

__global__ void k_scatter(const int* __restrict__ ei) {
    int e = blockIdx.x * blockDim.x + threadIdx.x;
    if (e < NE) {
        int r = ei[e];
        int c = ei[NE + e];
        int s = atomicAdd(&g_cnt[c], 1);
        g_src[s] = r;
        g_w[s]   = g_dis[r] * g_dis[c];
    }
}

// ------------------------- SpMM: t = 0.5 * (D^-1/2 A_hat D^-1/2) h --------
// one warp per destination node; each lane owns 8 features (2 float4)
__global__ void __launch_bounds__(256) k_spmm(int use_x0) {
    if (blockIdx.x == 0 && threadIdx.x == 0) { g_acc[0] = 0.0; g_acc[1] = 0.0; }
    int warp = (blockIdx.x * blockDim.x + threadIdx.x) >> 5;
    int lane = threadIdx.x & 31;
    if (warp >= NN) return;
    const float* __restrict__ h = use_x0 ? g_x0 : g_h;
    int c = warp;
    float dc = g_dis[c];
    float wself = dc * dc;
    const float4* hr = (const float4*)(h + (size_t)c * D_HID);
    float4 a0 = hr[lane], a1 = hr[lane + 32];
    a0.x *= wself; a0.y *= wself; a0.z *= wself; a0.w *= wself;
    a1.x *= wself; a1.y *= wself; a1.z *= wself; a1.w *= wself;
    int beg = g_rowptr[c], end = g_rowptr[c + 1];
    for (int e = beg; e < end; e++) {
        int   s = __ldg(&g_src[e]);
        float w = __ldg(&g_w[e]);
        const float4* hs = (const float4*)(h + (size_t)s * D_HID);
        float4 b0 = __ldg(&hs[lane]);
        float4 b1 = __ldg(&hs[lane + 32]);
        a0.x += w * b0.x; a0.y += w * b0.y; a0.z += w * b0.z; a0.w += w * b0.w;
        a1.x += w * b1.x; a1.y += w * b1.y; a1.z += w * b1.z; a1.w += w * b1.w;
    }
    float4* tr = (float4*)(g_t + (size_t)c * D_HID);
    a0.x *= 0.5f; a0.y *= 0.5f; a0.z *= 0.5f; a0.w *= 0.5f;
    a1.x *= 0.5f; a1.y *= 0.5f; a1.z *= 0.5f; a1.w *= 0.5f;
    tr[lane] = a0; tr[lane + 32] = a1;
}

// ------------------------- GEMM tiles -------------------------
#define BM 128
#define BN 128
#define BK 8
#define TM 8
#define TN 8

// MODE 0: C = relu(A @ B + bias)   (a_sel: 0=arg A, 1=g_h ; c_sel: 0=arg C, 1=g_x0)
__global__ void __launch_bounds__(256) k_gemm_lin(
    const float* __restrict__ Aarg, const float* __restrict__ B,
    const float* __restrict__ bias, float* __restrict__ Carg,
    int M, int N, int K, int a_sel, int c_sel)
{
    __shared__ float As[BK][BM];
    __shared__ float Bs[BK][BN];
    const float* A = a_sel ? g_h : Aarg;
    float* C = c_sel ? g_x0 : Carg;
    int tid = threadIdx.x;
    int tx = tid & 15, ty = tid >> 4;
    int m0 = blockIdx.y * BM, n0 = blockIdx.x * BN;
    int arow = tid >> 1, acol = (tid & 1) * 4;
    int brow = tid >> 5, bcol = (tid & 31) * 4;
    float acc[TM][TN];
#pragma unroll
    for (int i = 0; i < TM; i++)
#pragma unroll
        for (int j = 0; j < TN; j++) acc[i][j] = 0.0f;

    for (int k0 = 0; k0 < K; k0 += BK) {
        float4 av = make_float4(0.f, 0.f, 0.f, 0.f);
        int gr = m0 + arow;
        if (gr < M) av = *(const float4*)(A + (size_t)gr * K + k0 + acol);
        As[acol + 0][arow] = av.x; As[acol + 1][arow] = av.y;
        As[acol + 2][arow] = av.z; As[acol + 3][arow] = av.w;
        *(float4*)(&Bs[brow][bcol]) = *(const float4*)(B + (size_t)(k0 + brow) * N + n0 + bcol);
        __syncthreads();
#pragma unroll
        for (int kk = 0; kk < BK; kk++) {
            float4 a0 = *(const float4*)(&As[kk][ty * TM]);
            float4 a1 = *(const float4*)(&As[kk][ty * TM + 4]);
            float4 b0 = *(const float4*)(&Bs[kk][tx * TN]);
            float4 b1 = *(const float4*)(&Bs[kk][tx * TN + 4]);
            float af[TM] = {a0.x, a0.y, a0.z, a0.w, a1.x, a1.y, a1.z, a1.w};
            float bf[TN] = {b0.x, b0.y, b0.z, b0.w, b1.x, b1.y, b1.z, b1.w};
#pragma unroll
            for (int i = 0; i < TM; i++)
#pragma unroll
                for (int j = 0; j < TN; j++) acc[i][j] += af[i] * bf[j];
        }
        __syncthreads();
    }
#pragma unroll
    for (int i = 0; i < TM; i++) {
        int r = m0 + ty * TM + i;
        if (r < M) {
#pragma unroll
            for (int j = 0; j < TN; j++) {
                int c = n0 + tx * TN + j;
                C[(size_t)r * N + c] = fmaxf(acc[i][j] + bias[c], 0.0f);
            }
        }
    }
}

// MODE 1: h_pre = (1-beta)*(t + 0.5*x0) + beta*(t@W1 + 0.5*x0@W2)
// writes g_h, accumulates global sum / sumsq
__global__ void __launch_bounds__(256) k_gemm_layer(
    const float* __restrict__ W1, const float* __restrict__ W2, float beta)
{
    const int M = NN, N = D_HID, K = D_HID;
    __shared__ float As[BK][BM];
    __shared__ float Bs[BK][BN];
    int tid = threadIdx.x;
    int tx = tid & 15, ty = tid >> 4;
    int m0 = blockIdx.y * BM, n0 = blockIdx.x * BN;
    int arow = tid >> 1, acol = (tid & 1) * 4;
    int brow = tid >> 5, bcol = (tid & 31) * 4;
    float acc[TM][TN];
#pragma unroll
    for (int i = 0; i < TM; i++)
#pragma unroll
        for (int j = 0; j < TN; j++) acc[i][j] = 0.0f;

    for (int k0 = 0; k0 < 2 * K; k0 += BK) {
        int phase = (k0 >= K);
        const float* Ap = phase ? g_x0 : g_t;
        const float* Bp = phase ? W2 : W1;
        int kl = k0 - phase * K;
        float4 av = make_float4(0.f, 0.f, 0.f, 0.f);
        int gr = m0 + arow;
        if (gr < M) av = *(const float4*)(Ap + (size_t)gr * K + kl + acol);
        if (phase) { av.x *= 0.5f; av.y *= 0.5f; av.z *= 0.5f; av.w *= 0.5f; }
        As[acol + 0][arow] = av.x; As[acol + 1][arow] = av.y;
        As[acol + 2][arow] = av.z; As[acol + 3][arow] = av.w;
        *(float4*)(&Bs[brow][bcol]) = *(const float4*)(Bp + (size_t)(kl + brow) * N + n0 + bcol);
        __syncthreads();
#pragma unroll
        for (int kk = 0; kk < BK; kk++) {
            float4 a0 = *(const float4*)(&As[kk][ty * TM]);
            float4 a1 = *(const float4*)(&As[kk][ty * TM + 4]);
            float4 b0 = *(const float4*)(&Bs[kk][tx * TN]);
            float4 b1 = *(const float4*)(&Bs[kk][tx * TN + 4]);
            float af[TM] = {a0.x, a0.y, a0.z, a0.w, a1.x, a1.y, a1.z, a1.w};
            float bf[TN] = {b0.x, b0.y, b0.z, b0.w, b1.x, b1.y, b1.z, b1.w};
#pragma unroll
            for (int i = 0; i < TM; i++)
#pragma unroll
                for (int j = 0; j < TN; j++) acc[i][j] += af[i] * bf[j];
        }
        __syncthreads();
    }

    float s = 0.0f, ss = 0.0f;
    float omb = 1.0f - beta;
#pragma unroll
    for (int i = 0; i < TM; i++) {
        int r = m0 + ty * TM + i;
        if (r < M) {
#pragma unroll
            for (int j = 0; j < TN; j++) {
                int c = n0 + tx * TN + j;
                size_t idx = (size_t)r * N + c;
                float pre = omb * (g_t[idx] + 0.5f * g_x0[idx]) + beta * acc[i][j];
                g_h[idx] = pre;
                s += pre; ss += pre * pre;
            }
        }
    }
    // block reduction -> double atomics
#pragma unroll
    for (int off = 16; off > 0; off >>= 1) {
        s  += __shfl_down_sync(0xffffffffu, s, off);
        ss += __shfl_down_sync(0xffffffffu, ss, off);
    }
    __shared__ float rs[8], rss[8];
    int lane = tid & 31, wid = tid >> 5;
    if (lane == 0) { rs[wid] = s; rss[wid] = ss; }
    __syncthreads();
    if (tid == 0) {
        float S = 0.f, SS = 0.f;
        for (int w = 0; w < 8; w++) { S += rs[w]; SS += rss[w]; }
        atomicAdd(&g_acc[0], (double)S);
        atomicAdd(&g_acc[1], (double)SS);
    }
}

// ------------------------- layernorm stats + apply -------------------------
__global__ void k_stats() {
    double cnt = (double)NN * (double)D_HID;
    double mu  = g_acc[0] / cnt;
    double var = g_acc[1] / cnt - mu * mu;
    if (var < 0.0) var = 0.0;
    g_stats[0] = (float)mu;
    g_stats[1] = (float)(1.0 / (sqrt(var) + 1e-5));
}

__global__ void k_norm(const float* __restrict__ gamma, const float* __restrict__ beta) {
    float mu = g_stats[0], inv = g_stats[1];
    size_t total = (size_t)NN * D_HID / 4;
    size_t stride = (size_t)gridDim.x * blockDim.x;
    for (size_t i = blockIdx.x * blockDim.x + threadIdx.x; i < total; i += stride) {
        float4 v = ((float4*)g_h)[i];
        int c = (int)((i * 4) & (D_HID - 1));
        v.x = fmaxf(gamma[c + 0] * ((v.x - mu) * inv) + beta[c + 0], 0.0f);
        v.y = fmaxf(gamma[c + 1] * ((v.y - mu) * inv) + beta[c + 1], 0.0f);
        v.z = fmaxf(gamma[c + 2] * ((v.z - mu) * inv) + beta[c + 2], 0.0f);
        v.w = fmaxf(gamma[c + 3] * ((v.w - mu) * inv) + beta[c + 3], 0.0f);
        ((float4*)g_h)[i] = v;
    }
}

// ------------------------- launch -------------------------
extern "C" void kernel_launch(void* const* d_in, const int* in_sizes, int n_in,
                              void* d_out, int out_size) {
    const float* x       = (const float*)d_in[0];
    const int*   ei      = (const int*)  d_in[1];
    const float* lin1_w  = (const float*)d_in[2];
    const float* lin1_b  = (const float*)d_in[3];
    const float* conv_w1 = (const float*)d_in[4];
    const float* conv_w2 = (const float*)d_in[5];
    const float* gamma   = (const float*)d_in[6];
    const float* betaa   = (const float*)d_in[7];
    const float* lin2_w  = (const float*)d_in[8];
    const float* lin2_b  = (const float*)d_in[9];
    float* out = (float*)d_out;

    // graph normalization + CSR build (by destination)
    k_init<<<(NN + 255) / 256, 256>>>();
    k_edge_count<<<(NE + 255) / 256, 256>>>(ei);
    k_rsqrt<<<(NN + 255) / 256, 256>>>();
    k_scan<<<1, 1024>>>();
    k_cursor<<<(NN + 255) / 256, 256>>>();
    k_scatter<<<(NE + 255) / 256, 256>>>(ei);

    // lin1 + relu -> g_x0
    {
        dim3 grid(D_HID / BN, (NN + BM - 1) / BM);
        k_gemm_lin<<<grid, 256>>>(x, lin1_w, lin1_b, nullptr,
                                  NN, D_HID, D_IN, /*a_sel=*/0, /*c_sel=*/1);
    }

    // 8 GCNII layers
    for (int l = 0; l < NL; l++) {
        float beta_l = (float)log(1.0 / (double)(l + 1) + 1.0);
        k_spmm<<<(NN + 7) / 8, 256>>>(l == 0 ? 1 : 0);
        dim3 grid(D_HID / BN, (NN + BM - 1) / BM);
        k_gemm_layer<<<grid, 256>>>(conv_w1 + (size_t)l * D_HID * D_HID,
                                    conv_w2 + (size_t)l * D_HID * D_HID,
                                    beta_l);
        k_stats<<<1, 1>>>();
        k_norm<<<1024, 256>>>(gamma + (size_t)l * D_HID, betaa + (size_t)l * D_HID);
    }

    // lin2 + relu -> out
    {
        dim3 grid(D_OUT / BN, (NN + BM - 1) / BM);
        k_gemm_lin<<<grid, 256>>>(nullptr, lin2_w, lin2_b, out,
                                  NN, D_OUT, D_HID, /*a_sel=*/1, /*c_sel=*/0);
    }
    (void)in_sizes; (void)n_in; (void)out_size;
}

// round 3
// speedup vs baseline: 1.6926x; 1.6926x over previous
#include <cuda_runtime.h>
#include <cuda_bf16.h>
#include <math.h>
#include <stdint.h>

#define NN   50000
#define NE   800000
#define D_IN 128
#define D_HID 256
#define D_OUT 128
#define NL   8

// ---------------- weight buffer layout (transposed, K-major [N][K]) ------
#define WB_L1   0                         // lin1: [256][128]
#define WB_LYR  32768                     // layers: 8 x [256][512]
#define WB_L2   (32768 + 8 * 131072)      // lin2: [128][256]
#define WB_TOT  (WB_L2 + 32768)

// ------------------------- static device scratch -------------------------
__device__ float  g_dis[NN];
__device__ int    g_rowptr[NN + 1];
__device__ int    g_cnt[NN];
__device__ int    g_src[NE];
__device__ float  g_w[NE];
__device__ float  g_x0[(size_t)NN * D_HID];
__device__ float  g_t [(size_t)NN * D_HID];
__device__ float  g_h [(size_t)NN * D_HID];
__device__ double g_acc[2];
__device__ float  g_stats[2];
// bf16 split operands
__device__ __nv_bfloat16 g_A_hi[(size_t)NN * 512];   // cols 0..255: t (or h) ; 256..511: 0.5*x0
__device__ __nv_bfloat16 g_A_lo[(size_t)NN * 512];
__device__ __nv_bfloat16 g_xin_hi[(size_t)NN * D_IN];
__device__ __nv_bfloat16 g_xin_lo[(size_t)NN * D_IN];
__device__ __nv_bfloat16 g_Bw_hi[WB_TOT];
__device__ __nv_bfloat16 g_Bw_lo[WB_TOT];

// ------------------------- helpers -------------------------
__device__ __forceinline__ uint32_t smem_u32(const void* p) {
    uint32_t a;
    asm("{ .reg .u64 t; cvta.to.shared.u64 t, %1; cvt.u32.u64 %0, t; }" : "=r"(a) : "l"(p));
    return a;
}
__device__ __forceinline__ void cp16(uint32_t dst, const void* src) {
    asm volatile("cp.async.cg.shared.global [%0], [%1], 16;" :: "r"(dst), "l"(src));
}
#define CP_COMMIT() asm volatile("cp.async.commit_group;" ::: "memory")
#define CP_WAIT1()  asm volatile("cp.async.wait_group 1;" ::: "memory")

__device__ __forceinline__ void ldm_x4(uint32_t* r, uint32_t addr) {
    asm volatile("ldmatrix.sync.aligned.m8n8.x4.shared.b16 {%0,%1,%2,%3}, [%4];"
                 : "=r"(r[0]), "=r"(r[1]), "=r"(r[2]), "=r"(r[3]) : "r"(addr));
}
__device__ __forceinline__ void ldm_x2(uint32_t* r, uint32_t addr) {
    asm volatile("ldmatrix.sync.aligned.m8n8.x2.shared.b16 {%0,%1}, [%2];"
                 : "=r"(r[0]), "=r"(r[1]) : "r"(addr));
}
__device__ __forceinline__ void mma16816(float* c, const uint32_t* a, const uint32_t* b) {
    asm volatile("mma.sync.aligned.m16n8k16.row.col.f32.bf16.bf16.f32 "
                 "{%0,%1,%2,%3}, {%4,%5,%6,%7}, {%8,%9}, {%0,%1,%2,%3};"
                 : "+f"(c[0]), "+f"(c[1]), "+f"(c[2]), "+f"(c[3])
                 : "r"(a[0]), "r"(a[1]), "r"(a[2]), "r"(a[3]), "r"(b[0]), "r"(b[1]));
}
__device__ __forceinline__ void split2(float v, __nv_bfloat16& h, __nv_bfloat16& l) {
    h = __float2bfloat16(v);
    l = __float2bfloat16(v - __bfloat162float(h));
}

// ------------------------- setup kernels -------------------------
__global__ void k_init() {
    int i = blockIdx.x * blockDim.x + threadIdx.x;
    if (i < NN) { g_dis[i] = 1.0f; g_cnt[i] = 0; }
}
__global__ void k_edge_count(const int* __restrict__ ei) {
    int e = blockIdx.x * blockDim.x + threadIdx.x;
    if (e < NE) {
        int c = ei[NE + e];
        atomicAdd(&g_dis[c], 1.0f);
        atomicAdd(&g_cnt[c], 1);
    }
}
__global__ void k_rsqrt() {
    int i = blockIdx.x * blockDim.x + threadIdx.x;
    if (i < NN) g_dis[i] = rsqrtf(g_dis[i]);
}
__global__ void k_scan() {
    __shared__ int wsum[32];
    const int CH = (NN + 1023) / 1024;  // 49
    int tid = threadIdx.x;
    int lo = tid * CH;
    int hi = min(lo + CH, NN);
    int sum = 0;
    for (int i = lo; i < hi; i++) sum += g_cnt[i];
    int lane = tid & 31, wid = tid >> 5;
    int v = sum;
#pragma unroll
    for (int o = 1; o < 32; o <<= 1) { int t = __shfl_up_sync(~0u, v, o); if (lane >= o) v += t; }
    if (lane == 31) wsum[wid] = v;
    __syncthreads();
    if (wid == 0) {
        int w = wsum[lane];
#pragma unroll
        for (int o = 1; o < 32; o <<= 1) { int t = __shfl_up_sync(~0u, w, o); if (lane >= o) w += t; }
        wsum[lane] = w;
    }
    __syncthreads();
    int run = v - sum + (wid > 0 ? wsum[wid - 1] : 0);
    for (int i = lo; i < hi; i++) { g_rowptr[i] = run; run += g_cnt[i]; }
    if (tid == (NN - 1) / CH) g_rowptr[NN] = run;
}
__global__ void k_cursor() {
    int i = blockIdx.x * blockDim.x + threadIdx.x;
    if (i < NN) g_cnt[i] = g_rowptr[i];
}
__global__ void k_scatter(const int* __restrict__ ei) {
    int e = blockIdx.x * blockDim.x + threadIdx.x;
    if (e < NE) {
        int r = ei[e];
        int c = ei[NE + e];
        int s = atomicAdd(&g_cnt[c], 1);
        g_src[s] = r;
        g_w[s]   = g_dis[r] * g_dis[c];
    }
}

// ------------------------- weight / input prep (bf16 splits) -------------
__global__ void k_prep_w(const float* __restrict__ lin1_w, const float* __restrict__ w1,
                         const float* __restrict__ w2, const float* __restrict__ lin2_w) {
    int idx = blockIdx.x * blockDim.x + threadIdx.x;
    if (idx >= WB_TOT) return;
    float v;
    if (idx < WB_LYR) {                       // lin1: [n=256][k=128]
        int n = idx >> 7, k = idx & 127;
        v = lin1_w[k * 256 + n];
    } else if (idx < WB_L2) {                 // layer l: [n=256][k=512]
        int r = idx - WB_LYR;
        int l = r >> 17;
        int q = r & 131071;
        int n = q >> 9, k = q & 511;
        v = (k < 256) ? w1[l * 65536 + k * 256 + n]
                      : w2[l * 65536 + (k - 256) * 256 + n];
    } else {                                  // lin2: [n=128][k=256]
        int r = idx - WB_L2;
        int n = r >> 8, k = r & 255;
        v = lin2_w[k * 128 + n];
    }
    __nv_bfloat16 h, l;
    split2(v, h, l);
    g_Bw_hi[idx] = h;
    g_Bw_lo[idx] = l;
}
__global__ void k_prep_x(const float* __restrict__ x) {
    size_t idx = (size_t)blockIdx.x * blockDim.x + threadIdx.x;
    if (idx >= (size_t)NN * D_IN) return;
    __nv_bfloat16 h, l;
    split2(x[idx], h, l);
    g_xin_hi[idx] = h;
    g_xin_lo[idx] = l;
}

// ------------------------- SpMM -------------------------
__global__ void __launch_bounds__(256) k_spmm(int use_x0) {
    if (blockIdx.x == 0 && threadIdx.x == 0) { g_acc[0] = 0.0; g_acc[1] = 0.0; }
    int warp = (blockIdx.x * blockDim.x + threadIdx.x) >> 5;
    int lane = threadIdx.x & 31;
    if (warp >= NN) return;
    const float* __restrict__ h = use_x0 ? g_x0 : g_h;
    int c = warp;
    float dc = g_dis[c];
    float wself = dc * dc;
    const float4* hr = (const float4*)(h + (size_t)c * D_HID);
    float4 a0 = hr[lane], a1 = hr[lane + 32];
    a0.x *= wself; a0.y *= wself; a0.z *= wself; a0.w *= wself;
    a1.x *= wself; a1.y *= wself; a1.z *= wself; a1.w *= wself;
    int beg = g_rowptr[c], end = g_rowptr[c + 1];
    for (int e = beg; e < end; e++) {
        int   s = __ldg(&g_src[e]);
        float w = __ldg(&g_w[e]);
        const float4* hs = (const float4*)(h + (size_t)s * D_HID);
        float4 b0 = __ldg(&hs[lane]);
        float4 b1 = __ldg(&hs[lane + 32]);
        a0.x += w * b0.x; a0.y += w * b0.y; a0.z += w * b0.z; a0.w += w * b0.w;
        a1.x += w * b1.x; a1.y += w * b1.y; a1.z += w * b1.z; a1.w += w * b1.w;
    }
    a0.x *= 0.5f; a0.y *= 0.5f; a0.z *= 0.5f; a0.w *= 0.5f;
    a1.x *= 0.5f; a1.y *= 0.5f; a1.z *= 0.5f; a1.w *= 0.5f;
    float4* tr = (float4*)(g_t + (size_t)c * D_HID);
    tr[lane] = a0; tr[lane + 32] = a1;
    __nv_bfloat16* Ah = g_A_hi + (size_t)c * 512;
    __nv_bfloat16* Al = g_A_lo + (size_t)c * 512;
    float vv[8] = {a0.x, a0.y, a0.z, a0.w, a1.x, a1.y, a1.z, a1.w};
    int cols[2] = {lane * 4, 128 + lane * 4};
#pragma unroll
    for (int g = 0; g < 2; g++) {
        __nv_bfloat16 h4[4], l4[4];
#pragma unroll
        for (int j = 0; j < 4; j++) split2(vv[g * 4 + j], h4[j], l4[j]);
        *(__nv_bfloat162*)(Ah + cols[g])     = __nv_bfloat162(h4[0], h4[1]);
        *(__nv_bfloat162*)(Ah + cols[g] + 2) = __nv_bfloat162(h4[2], h4[3]);
        *(__nv_bfloat162*)(Al + cols[g])     = __nv_bfloat162(l4[0], l4[1]);
        *(__nv_bfloat162*)(Al + cols[g] + 2) = __nv_bfloat162(l4[2], l4[3]);
    }
}

// ------------------------- mma.sync GEMM -------------------------
// 128x128 CTA tile, 8 warps (2x4), warp tile 64x32, BK=32, double-buffered cp.async.
// SMEM stage layout (per stage, 40960B):
//   A_hi [128 rows x 80B], A_lo (+10240), B_hi (+20480), B_lo (+30720)
// mode 1: lin1  A=xin (lda=128), K=128, N=256 : relu(acc+bias)->g_x0 + 0.5x0 splits
// mode 2: layer A=g_A (lda=512), K=512, N=256 : pre->g_h + global sums
// mode 3: lin2  A=g_A (lda=512), K=256, N=128 : relu(acc+bias)->Cout
#define STG_SZ 40960
#define SM_TOTAL (2 * STG_SZ)

__global__ void __launch_bounds__(256) k_mma(int mode, int bOff, int K, int N,
                                             const float* __restrict__ bias,
                                             float* __restrict__ Cout, float beta) {
    extern __shared__ char smem[];
    uint32_t sb = smem_u32(smem);
    int tid = threadIdx.x;
    int lane = tid & 31, wrp = tid >> 5;
    int wm = wrp & 1, wn = wrp >> 1;
    int m0 = blockIdx.y * 128, n0 = blockIdx.x * 128;

    const __nv_bfloat16* Ahi = (mode == 1) ? g_xin_hi : g_A_hi;
    const __nv_bfloat16* Alo = (mode == 1) ? g_xin_lo : g_A_lo;
    const int lda = (mode == 1) ? 128 : 512;
    const __nv_bfloat16* Bhi = g_Bw_hi + bOff;
    const __nv_bfloat16* Blo = g_Bw_lo + bOff;

    const int nch = K / 32;

    // per-thread load coords: 2 iterations x (row=idx/4, seg=idx%4), 16B each
    int r0i = tid >> 2, seg0 = (tid & 3);
    int r1i = (tid + 256) >> 2, seg1 = seg0;

    // prefetch macro-ish lambda
    auto load_stage = [&](int s, int ch) {
        int kb = ch * 32;
        uint32_t base = sb + s * STG_SZ;
        // A rows (clamped), B rows always valid
        int gr0 = m0 + r0i; if (gr0 >= NN) gr0 = 0;
        int gr1 = m0 + r1i; if (gr1 >= NN) gr1 = 0;
        const __nv_bfloat16* a0h = Ahi + (size_t)gr0 * lda + kb + seg0 * 8;
        const __nv_bfloat16* a1h = Ahi + (size_t)gr1 * lda + kb + seg1 * 8;
        const __nv_bfloat16* a0l = Alo + (size_t)gr0 * lda + kb + seg0 * 8;
        const __nv_bfloat16* a1l = Alo + (size_t)gr1 * lda + kb + seg1 * 8;
        uint32_t d0 = base + r0i * 80 + seg0 * 16;
        uint32_t d1 = base + r1i * 80 + seg1 * 16;
        cp16(d0, a0h);          cp16(d1, a1h);
        cp16(d0 + 10240, a0l);  cp16(d1 + 10240, a1l);
        const __nv_bfloat16* b0h = Bhi + (size_t)(n0 + r0i) * K + kb + seg0 * 8;
        const __nv_bfloat16* b1h = Bhi + (size_t)(n0 + r1i) * K + kb + seg1 * 8;
        const __nv_bfloat16* b0l = Blo + (size_t)(n0 + r0i) * K + kb + seg0 * 8;
        const __nv_bfloat16* b1l = Blo + (size_t)(n0 + r1i) * K + kb + seg1 * 8;
        cp16(d0 + 20480, b0h);  cp16(d1 + 20480, b1h);
        cp16(d0 + 30720, b0l);  cp16(d1 + 30720, b1l);
    };

    float acc[4][4][4];
#pragma unroll
    for (int i = 0; i < 4; i++)
#pragma unroll
        for (int j = 0; j < 4; j++)
#pragma unroll
            for (int q = 0; q < 4; q++) acc[i][j][q] = 0.0f;

    load_stage(0, 0); CP_COMMIT();
    if (nch > 1) load_stage(1, 1);
    CP_COMMIT();

    // ldmatrix lane address components
    int a_row = wm * 64 + (lane & 7) + ((lane >> 3) & 1) * 8;
    int a_colh = (lane >> 4) * 8;
    int b_row = wn * 32 + (lane & 7);
    int b_colh = ((lane >> 3) & 1) * 8;

    for (int ch = 0; ch < nch; ch++) {
        int st = ch & 1;
        CP_WAIT1();
        __syncthreads();
        uint32_t base = sb + st * STG_SZ;
#pragma unroll
        for (int k16 = 0; k16 < 2; k16++) {
            uint32_t ah[4][4], al[4][4], bh[4][2], bl[4][2];
#pragma unroll
            for (int mt = 0; mt < 4; mt++) {
                uint32_t ad = base + (a_row + mt * 16) * 80 + (k16 * 16 + a_colh) * 2;
                ldm_x4(ah[mt], ad);
                ldm_x4(al[mt], ad + 10240);
            }
#pragma unroll
            for (int nt = 0; nt < 4; nt++) {
                uint32_t bd = base + 20480 + (b_row + nt * 8) * 80 + (k16 * 16 + b_colh) * 2;
                ldm_x2(bh[nt], bd);
                ldm_x2(bl[nt], bd + 10240);
            }
#pragma unroll
            for (int mt = 0; mt < 4; mt++)
#pragma unroll
                for (int nt = 0; nt < 4; nt++) {
                    mma16816(acc[mt][nt], ah[mt], bh[nt]);
                    mma16816(acc[mt][nt], al[mt], bh[nt]);
                    mma16816(acc[mt][nt], ah[mt], bl[nt]);
                }
        }
        __syncthreads();
        if (ch + 2 < nch) load_stage(st, ch + 2);
        CP_COMMIT();
    }

    // ------------- epilogue -------------
    float sum = 0.0f, ssum = 0.0f;
    float omb = 1.0f - beta;
    int rbase = m0 + wm * 64 + (lane >> 2);
    int cbase = n0 + wn * 32 + (lane & 3) * 2;
#pragma unroll
    for (int mt = 0; mt < 4; mt++) {
#pragma unroll
        for (int half = 0; half < 2; half++) {
            int row = rbase + mt * 16 + half * 8;
            if (row >= NN) continue;
#pragma unroll
            for (int nt = 0; nt < 4; nt++) {
                int c = cbase + nt * 8;
                float v0 = acc[mt][nt][half * 2 + 0];
                float v1 = acc[mt][nt][half * 2 + 1];
                if (mode == 2) {
                    size_t idx = (size_t)row * 256 + c;
                    float2 tv = *(const float2*)(g_t + idx);
                    float2 xv = *(const float2*)(g_x0 + idx);
                    float p0 = omb * (tv.x + 0.5f * xv.x) + beta * v0;
                    float p1 = omb * (tv.y + 0.5f * xv.y) + beta * v1;
                    *(float2*)(g_h + idx) = make_float2(p0, p1);
                    sum += p0 + p1;
                    ssum += p0 * p0 + p1 * p1;
                } else if (mode == 1) {
                    float r0 = fmaxf(v0 + __ldg(&bias[c]), 0.0f);
                    float r1 = fmaxf(v1 + __ldg(&bias[c + 1]), 0.0f);
                    *(float2*)(g_x0 + (size_t)row * 256 + c) = make_float2(r0, r1);
                    __nv_bfloat16 h0, l0, h1, l1;
                    split2(0.5f * r0, h0, l0);
                    split2(0.5f * r1, h1, l1);
                    size_t sidx = (size_t)row * 512 + 256 + c;
                    *(__nv_bfloat162*)(g_A_hi + sidx) = __nv_bfloat162(h0, h1);
                    *(__nv_bfloat162*)(g_A_lo + sidx) = __nv_bfloat162(l0, l1);
                } else {
                    float r0 = fmaxf(v0 + __ldg(&bias[c]), 0.0f);
                    float r1 = fmaxf(v1 + __ldg(&bias[c + 1]), 0.0f);
                    *(float2*)(Cout + (size_t)row * N + c) = make_float2(r0, r1);
                }
            }
        }
    }
    if (mode == 2) {
#pragma unroll
        for (int off = 16; off > 0; off >>= 1) {
            sum  += __shfl_down_sync(0xffffffffu, sum, off);
            ssum += __shfl_down_sync(0xffffffffu, ssum, off);
        }
        __syncthreads();
        float* rs  = (float*)smem;
        float* rss = (float*)smem + 32;
        if (lane == 0) { rs[wrp] = sum; rss[wrp] = ssum; }
        __syncthreads();
        if (tid == 0) {
            float S = 0.f, SS = 0.f;
            for (int w = 0; w < 8; w++) { S += rs[w]; SS += rss[w]; }
            atomicAdd(&g_acc[0], (double)S);
            atomicAdd(&g_acc[1], (double)SS);
        }
    }
}

// ------------------------- layernorm stats + apply -------------------------
__global__ void k_stats() {
    double cnt = (double)NN * (double)D_HID;
    double mu  = g_acc[0] / cnt;
    double var = g_acc[1] / cnt - mu * mu;
    if (var < 0.0) var = 0.0;
    g_stats[0] = (float)mu;
    g_stats[1] = (float)(1.0 / (sqrt(var) + 1e-5));
}

__global__ void k_norm(const float* __restrict__ gamma, const float* __restrict__ beta,
                       int write_split) {
    float mu = g_stats[0], inv = g_stats[1];
    size_t total = (size_t)NN * D_HID / 4;
    size_t stride = (size_t)gridDim.x * blockDim.x;
    for (size_t i = blockIdx.x * blockDim.x + threadIdx.x; i < total; i += stride) {
        float4 v = ((float4*)g_h)[i];
        int c = (int)((i * 4) & (D_HID - 1));
        v.x = fmaxf(gamma[c + 0] * ((v.x - mu) * inv) + beta[c + 0], 0.0f);
        v.y = fmaxf(gamma[c + 1] * ((v.y - mu) * inv) + beta[c + 1], 0.0f);
        v.z = fmaxf(gamma[c + 2] * ((v.z - mu) * inv) + beta[c + 2], 0.0f);
        v.w = fmaxf(gamma[c + 3] * ((v.w - mu) * inv) + beta[c + 3], 0.0f);
        ((float4*)g_h)[i] = v;
        if (write_split) {
            size_t row = (i * 4) >> 8;
            size_t base = row * 512 + c;
            __nv_bfloat16 h4[4], l4[4];
            split2(v.x, h4[0], l4[0]); split2(v.y, h4[1], l4[1]);
            split2(v.z, h4[2], l4[2]); split2(v.w, h4[3], l4[3]);
            *(__nv_bfloat162*)(g_A_hi + base)     = __nv_bfloat162(h4[0], h4[1]);
            *(__nv_bfloat162*)(g_A_hi + base + 2) = __nv_bfloat162(h4[2], h4[3]);
            *(__nv_bfloat162*)(g_A_lo + base)     = __nv_bfloat162(l4[0], l4[1]);
            *(__nv_bfloat162*)(g_A_lo + base + 2) = __nv_bfloat162(l4[2], l4[3]);
        }
    }
}

// ------------------------- launch -------------------------
extern "C" void kernel_launch(void* const* d_in, const int* in_sizes, int n_in,
                              void* d_out, int out_size) {
    const float* x       = (const float*)d_in[0];
    const int*   ei      = (const int*)  d_in[1];
    const float* lin1_w  = (const float*)d_in[2];
    const float* lin1_b  = (const float*)d_in[3];
    const float* conv_w1 = (const float*)d_in[4];
    const float* conv_w2 = (const float*)d_in[5];
    const float* gamma   = (const float*)d_in[6];
    const float* betaa   = (const float*)d_in[7];
    const float* lin2_w  = (const float*)d_in[8];
    const float* lin2_b  = (const float*)d_in[9];
    float* out = (float*)d_out;

    static int smem_set = 0;
    if (!smem_set) {
        cudaFuncSetAttribute(k_mma, cudaFuncAttributeMaxDynamicSharedMemorySize, SM_TOTAL);
        smem_set = 1;
    }

    // graph normalization + CSR build
    k_init<<<(NN + 255) / 256, 256>>>();
    k_edge_count<<<(NE + 255) / 256, 256>>>(ei);
    k_rsqrt<<<(NN + 255) / 256, 256>>>();
    k_scan<<<1, 1024>>>();
    k_cursor<<<(NN + 255) / 256, 256>>>();
    k_scatter<<<(NE + 255) / 256, 256>>>(ei);

    // bf16 operand prep
    k_prep_w<<<(WB_TOT + 255) / 256, 256>>>(lin1_w, conv_w1, conv_w2, lin2_w);
    k_prep_x<<<(NN * D_IN + 255) / 256, 256>>>(x);

    const int MT = (NN + 127) / 128;  // 391

    // lin1 + relu -> g_x0 (+ 0.5*x0 splits)
    k_mma<<<dim3(2, MT), 256, SM_TOTAL>>>(1, WB_L1, 128, 256, lin1_b, nullptr, 0.0f);

    // 8 GCNII layers
    for (int l = 0; l < NL; l++) {
        float beta_l = (float)log(1.0 / (double)(l + 1) + 1.0);
        k_spmm<<<(NN + 7) / 8, 256>>>(l == 0 ? 1 : 0);
        k_mma<<<dim3(2, MT), 256, SM_TOTAL>>>(2, WB_LYR + l * 131072, 512, 256,
                                              nullptr, nullptr, beta_l);
        k_stats<<<1, 1>>>();
        k_norm<<<1024, 256>>>(gamma + (size_t)l * D_HID, betaa + (size_t)l * D_HID,
                              (l == NL - 1) ? 1 : 0);
    }

    // lin2 + relu -> out
    k_mma<<<dim3(1, MT), 256, SM_TOTAL>>>(3, WB_L2, 256, 128, lin2_b, out, 0.0f);

    (void)in_sizes; (void)n_in; (void)out_size;
}

// round 4
// speedup vs baseline: 1.7997x; 1.0632x over previous
#include <cuda_runtime.h>
#include <cuda_bf16.h>
#include <math.h>
#include <stdint.h>

#define NN   50000
#define NE   800000
#define D_IN 128
#define D_HID 256
#define D_OUT 128
#define NL   8

// ---------------- weight buffer layout (transposed, K-major [N][K]) ------
#define WB_L1   0                         // lin1: [256][128]
#define WB_LYR  32768                     // layers: 8 x [256][512]  (W' = beta*W + omb*I)
#define WB_L2   (32768 + 8 * 131072)      // lin2: [128][256]
#define WB_TOT  (WB_L2 + 32768)

// ------------------------- static device scratch -------------------------
__device__ float  g_dis[NN];
__device__ int    g_rowptr[NN + 1];
__device__ int    g_cnt[NN];
__device__ int    g_bsum[64];
__device__ int    g_boff[64];
__device__ int    g_src[NE];
__device__ float  g_w[NE];
__device__ float  g_x0[(size_t)NN * D_HID];
__device__ float  g_h [(size_t)NN * D_HID];
__device__ double g_accA[2][2];           // [parity][sum, sumsq]
// bf16 split operands
__device__ __nv_bfloat16 g_A_hi[(size_t)NN * 512];   // cols 0..255: t (or h_norm) ; 256..511: 0.5*x0
__device__ __nv_bfloat16 g_A_lo[(size_t)NN * 512];
__device__ __nv_bfloat16 g_xin_hi[(size_t)NN * D_IN];
__device__ __nv_bfloat16 g_xin_lo[(size_t)NN * D_IN];
__device__ __nv_bfloat16 g_Bw_hi[WB_TOT];
__device__ __nv_bfloat16 g_Bw_lo[WB_TOT];

// ------------------------- helpers -------------------------
__device__ __forceinline__ uint32_t smem_u32(const void* p) {
    uint32_t a;
    asm("{ .reg .u64 t; cvta.to.shared.u64 t, %1; cvt.u32.u64 %0, t; }" : "=r"(a) : "l"(p));
    return a;
}
__device__ __forceinline__ void cp16(uint32_t dst, const void* src) {
    asm volatile("cp.async.cg.shared.global [%0], [%1], 16;" :: "r"(dst), "l"(src));
}
#define CP_COMMIT() asm volatile("cp.async.commit_group;" ::: "memory")
#define CP_WAIT1()  asm volatile("cp.async.wait_group 1;" ::: "memory")

__device__ __forceinline__ void ldm_x4(uint32_t* r, uint32_t addr) {
    asm volatile("ldmatrix.sync.aligned.m8n8.x4.shared.b16 {%0,%1,%2,%3}, [%4];"
                 : "=r"(r[0]), "=r"(r[1]), "=r"(r[2]), "=r"(r[3]) : "r"(addr));
}
__device__ __forceinline__ void ldm_x2(uint32_t* r, uint32_t addr) {
    asm volatile("ldmatrix.sync.aligned.m8n8.x2.shared.b16 {%0,%1}, [%2];"
                 : "=r"(r[0]), "=r"(r[1]) : "r"(addr));
}
__device__ __forceinline__ void mma16816(float* c, const uint32_t* a, const uint32_t* b) {
    asm volatile("mma.sync.aligned.m16n8k16.row.col.f32.bf16.bf16.f32 "
                 "{%0,%1,%2,%3}, {%4,%5,%6,%7}, {%8,%9}, {%0,%1,%2,%3};"
                 : "+f"(c[0]), "+f"(c[1]), "+f"(c[2]), "+f"(c[3])
                 : "r"(a[0]), "r"(a[1]), "r"(a[2]), "r"(a[3]), "r"(b[0]), "r"(b[1]));
}
__device__ __forceinline__ void split2(float v, __nv_bfloat16& h, __nv_bfloat16& l) {
    h = __float2bfloat16(v);
    l = __float2bfloat16(v - __bfloat162float(h));
}

// ------------------------- setup kernels -------------------------
__global__ void k_init() {
    int i = blockIdx.x * blockDim.x + threadIdx.x;
    if (i < NN) { g_dis[i] = 1.0f; g_cnt[i] = 0; }
}
__global__ void k_edge_count(const int* __restrict__ ei) {
    int e = blockIdx.x * blockDim.x + threadIdx.x;
    if (e < NE) {
        int c = ei[NE + e];
        atomicAdd(&g_dis[c], 1.0f);
        atomicAdd(&g_cnt[c], 1);
    }
}
__global__ void k_rsqrt() {
    int i = blockIdx.x * blockDim.x + threadIdx.x;
    if (i < NN) g_dis[i] = rsqrtf(g_dis[i]);
}
// ---- parallel scan: part sums -> top scan -> block scan ----
__device__ __forceinline__ int block_scan_inc(int v, int* wsum) {
    int lane = threadIdx.x & 31, wid = threadIdx.x >> 5;
#pragma unroll
    for (int o = 1; o < 32; o <<= 1) { int t = __shfl_up_sync(~0u, v, o); if (lane >= o) v += t; }
    if (lane == 31) wsum[wid] = v;
    __syncthreads();
    if (wid == 0) {
        int w = (lane < 32) ? wsum[lane] : 0;
#pragma unroll
        for (int o = 1; o < 32; o <<= 1) { int t = __shfl_up_sync(~0u, w, o); if (lane >= o) w += t; }
        wsum[lane] = w;
    }
    __syncthreads();
    return v + (wid > 0 ? wsum[wid - 1] : 0);
}
__global__ void k_scan_part() {
    __shared__ int wsum[32];
    int i = blockIdx.x * 1024 + threadIdx.x;
    int v = (i < NN) ? g_cnt[i] : 0;
    int inc = block_scan_inc(v, wsum);
    if (threadIdx.x == 1023) g_bsum[blockIdx.x] = inc;
}
__global__ void k_scan_top() {
    int tid = threadIdx.x;  // 64 threads
    int v = (tid < 49) ? g_bsum[tid] : 0;
#pragma unroll
    for (int o = 1; o < 64; o <<= 1) { int t = __shfl_up_sync(~0u, v & 0, 0); (void)t; break; }
    // simple serial by thread 0 (49 values)
    if (tid == 0) {
        int run = 0;
        for (int b = 0; b < 49; b++) { g_boff[b] = run; run += g_bsum[b]; }
        g_rowptr[NN] = run;
    }
}
__global__ void k_scan_out() {
    __shared__ int wsum[32];
    int i = blockIdx.x * 1024 + threadIdx.x;
    int v = (i < NN) ? g_cnt[i] : 0;
    int inc = block_scan_inc(v, wsum);
    if (i < NN) g_rowptr[i] = g_boff[blockIdx.x] + inc - v;   // exclusive
}
__global__ void k_cursor() {
    int i = blockIdx.x * blockDim.x + threadIdx.x;
    if (i < NN) g_cnt[i] = g_rowptr[i];
}
__global__ void k_scatter(const int* __restrict__ ei) {
    int e = blockIdx.x * blockDim.x + threadIdx.x;
    if (e < NE) {
        int r = ei[e];
        int c = ei[NE + e];
        int s = atomicAdd(&g_cnt[c], 1);
        g_src[s] = r;
        g_w[s]   = g_dis[r] * g_dis[c];
    }
}

// ------------------------- weight / input prep (bf16 splits) -------------
// layer weights are fused: W1' = beta*W1 + (1-beta)*I ; W2' = beta*W2 + (1-beta)*I
__global__ void k_prep_w(const float* __restrict__ lin1_w, const float* __restrict__ w1,
                         const float* __restrict__ w2, const float* __restrict__ lin2_w) {
    int idx = blockIdx.x * blockDim.x + threadIdx.x;
    if (idx >= WB_TOT) return;
    float v;
    if (idx < WB_LYR) {                       // lin1: [n=256][k=128]
        int n = idx >> 7, k = idx & 127;
        v = lin1_w[k * 256 + n];
    } else if (idx < WB_L2) {                 // layer l: [n=256][k=512]
        int r = idx - WB_LYR;
        int l = r >> 17;
        int q = r & 131071;
        int n = q >> 9, k = q & 511;
        float beta = logf((float)(l + 2) / (float)(l + 1));
        float omb = 1.0f - beta;
        if (k < 256) v = beta * w1[l * 65536 + k * 256 + n] + ((k == n) ? omb : 0.0f);
        else {
            int k2 = k - 256;
            v = beta * w2[l * 65536 + k2 * 256 + n] + ((k2 == n) ? omb : 0.0f);
        }
    } else {                                  // lin2: [n=128][k=256]
        int r = idx - WB_L2;
        int n = r >> 8, k = r & 255;
        v = lin2_w[k * 128 + n];
    }
    __nv_bfloat16 h, l;
    split2(v, h, l);
    g_Bw_hi[idx] = h;
    g_Bw_lo[idx] = l;
}
__global__ void k_prep_x(const float* __restrict__ x) {
    size_t idx = (size_t)blockIdx.x * blockDim.x + threadIdx.x;
    if (idx >= (size_t)NN * D_IN) return;
    __nv_bfloat16 h, l;
    split2(x[idx], h, l);
    g_xin_hi[idx] = h;
    g_xin_lo[idx] = l;
}

// ------------------------- SpMM with fused norm+relu on gather -----------
// layer l: gathers from (l==0 ? g_x0 : g_h) applying eta(v) = max(a*v+b, 0)
// where a = gamma*inv, b = beta - mu*a of layer l-1 (identity for l==0).
// Writes bf16 splits of t = 0.5*agg into g_A_hi/lo cols 0..255.
// Resets g_accA[l&1] for the following GEMM.
__global__ void __launch_bounds__(256) k_spmm(int l, const float* __restrict__ gam,
                                              const float* __restrict__ bet) {
    int par = l & 1;
    if (blockIdx.x == 0 && threadIdx.x == 0) { g_accA[par][0] = 0.0; g_accA[par][1] = 0.0; }
    int warp = (blockIdx.x * blockDim.x + threadIdx.x) >> 5;
    int lane = threadIdx.x & 31;
    if (warp >= NN) return;
    const float* __restrict__ h = (l == 0) ? g_x0 : g_h;

    // per-lane norm coefficients for 8 owned columns
    float4 ca0, cb0, ca1, cb1;
    if (l == 0) {
        ca0 = ca1 = make_float4(1.f, 1.f, 1.f, 1.f);
        cb0 = cb1 = make_float4(0.f, 0.f, 0.f, 0.f);
    } else {
        int pp = (l - 1) & 1;
        double cnt = (double)NN * (double)D_HID;
        double mu = g_accA[pp][0] / cnt;
        double var = g_accA[pp][1] / cnt - mu * mu;
        if (var < 0.0) var = 0.0;
        float inv = (float)(1.0 / (sqrt(var) + 1e-5));
        float muf = (float)mu;
        int c0 = lane * 4, c1 = 128 + lane * 4;
        float4 g0 = *(const float4*)(gam + c0), g1 = *(const float4*)(gam + c1);
        float4 b0 = *(const float4*)(bet + c0), b1 = *(const float4*)(bet + c1);
        ca0 = make_float4(g0.x * inv, g0.y * inv, g0.z * inv, g0.w * inv);
        ca1 = make_float4(g1.x * inv, g1.y * inv, g1.z * inv, g1.w * inv);
        cb0 = make_float4(b0.x - muf * ca0.x, b0.y - muf * ca0.y, b0.z - muf * ca0.z, b0.w - muf * ca0.w);
        cb1 = make_float4(b1.x - muf * ca1.x, b1.y - muf * ca1.y, b1.z - muf * ca1.z, b1.w - muf * ca1.w);
    }

    int c = warp;
    float dc = g_dis[c];
    float wself = dc * dc;
    const float4* hr = (const float4*)(h + (size_t)c * D_HID);
    float4 v0 = hr[lane], v1 = hr[lane + 32];
    // eta(self)
    float4 e0, e1;
    e0.x = fmaxf(ca0.x * v0.x + cb0.x, 0.f); e0.y = fmaxf(ca0.y * v0.y + cb0.y, 0.f);
    e0.z = fmaxf(ca0.z * v0.z + cb0.z, 0.f); e0.w = fmaxf(ca0.w * v0.w + cb0.w, 0.f);
    e1.x = fmaxf(ca1.x * v1.x + cb1.x, 0.f); e1.y = fmaxf(ca1.y * v1.y + cb1.y, 0.f);
    e1.z = fmaxf(ca1.z * v1.z + cb1.z, 0.f); e1.w = fmaxf(ca1.w * v1.w + cb1.w, 0.f);
    float4 a0, a1;
    a0.x = wself * e0.x; a0.y = wself * e0.y; a0.z = wself * e0.z; a0.w = wself * e0.w;
    a1.x = wself * e1.x; a1.y = wself * e1.y; a1.z = wself * e1.z; a1.w = wself * e1.w;

    int beg = g_rowptr[c], end = g_rowptr[c + 1];
#pragma unroll 2
    for (int e = beg; e < end; e++) {
        int   s = __ldg(&g_src[e]);
        float w = __ldg(&g_w[e]);
        const float4* hs = (const float4*)(h + (size_t)s * D_HID);
        float4 b0 = __ldg(&hs[lane]);
        float4 b1 = __ldg(&hs[lane + 32]);
        a0.x += w * fmaxf(ca0.x * b0.x + cb0.x, 0.f);
        a0.y += w * fmaxf(ca0.y * b0.y + cb0.y, 0.f);
        a0.z += w * fmaxf(ca0.z * b0.z + cb0.z, 0.f);
        a0.w += w * fmaxf(ca0.w * b0.w + cb0.w, 0.f);
        a1.x += w * fmaxf(ca1.x * b1.x + cb1.x, 0.f);
        a1.y += w * fmaxf(ca1.y * b1.y + cb1.y, 0.f);
        a1.z += w * fmaxf(ca1.z * b1.z + cb1.z, 0.f);
        a1.w += w * fmaxf(ca1.w * b1.w + cb1.w, 0.f);
    }
    // t = 0.5 * agg -> bf16 splits only
    __nv_bfloat16* Ah = g_A_hi + (size_t)c * 512;
    __nv_bfloat16* Al = g_A_lo + (size_t)c * 512;
    float vv[8] = {0.5f * a0.x, 0.5f * a0.y, 0.5f * a0.z, 0.5f * a0.w,
                   0.5f * a1.x, 0.5f * a1.y, 0.5f * a1.z, 0.5f * a1.w};
    int cols[2] = {lane * 4, 128 + lane * 4};
#pragma unroll
    for (int g = 0; g < 2; g++) {
        __nv_bfloat16 h4[4], l4[4];
#pragma unroll
        for (int j = 0; j < 4; j++) split2(vv[g * 4 + j], h4[j], l4[j]);
        *(__nv_bfloat162*)(Ah + cols[g])     = __nv_bfloat162(h4[0], h4[1]);
        *(__nv_bfloat162*)(Ah + cols[g] + 2) = __nv_bfloat162(h4[2], h4[3]);
        *(__nv_bfloat162*)(Al + cols[g])     = __nv_bfloat162(l4[0], l4[1]);
        *(__nv_bfloat162*)(Al + cols[g] + 2) = __nv_bfloat162(l4[2], l4[3]);
    }
}

// ------------------------- mma.sync GEMM (3-stage pipeline) --------------
// 128x128 CTA tile, 8 warps (2x4), warp 64x32, BK=32.
// mode 1: lin1  A=xin (lda=128), K=128, N=256 : relu(acc+bias)->g_x0 + 0.5x0 splits
// mode 2: layer A=g_A (lda=512), K=512, N=256 : acc->g_h + global sums (W' pre-fused)
// mode 3: lin2  A=g_A (lda=512), K=256, N=128 : relu(acc+bias)->Cout
#define STG_SZ 40960
#define NSTG 3
#define SM_TOTAL (NSTG * STG_SZ)

__global__ void __launch_bounds__(256) k_mma(int mode, int bOff, int K, int N,
                                             const float* __restrict__ bias,
                                             float* __restrict__ Cout, int parity) {
    extern __shared__ char smem[];
    uint32_t sb = smem_u32(smem);
    int tid = threadIdx.x;
    int lane = tid & 31, wrp = tid >> 5;
    int wm = wrp & 1, wn = wrp >> 1;
    int m0 = blockIdx.y * 128, n0 = blockIdx.x * 128;

    const __nv_bfloat16* Ahi = (mode == 1) ? g_xin_hi : g_A_hi;
    const __nv_bfloat16* Alo = (mode == 1) ? g_xin_lo : g_A_lo;
    const int lda = (mode == 1) ? 128 : 512;
    const __nv_bfloat16* Bhi = g_Bw_hi + bOff;
    const __nv_bfloat16* Blo = g_Bw_lo + bOff;

    const int nch = K / 32;

    int r0i = tid >> 2, seg0 = (tid & 3);
    int r1i = (tid + 256) >> 2;

    auto load_stage = [&](int s, int ch) {
        int kb = ch * 32;
        uint32_t base = sb + s * STG_SZ;
        int gr0 = m0 + r0i; if (gr0 >= NN) gr0 = 0;
        int gr1 = m0 + r1i; if (gr1 >= NN) gr1 = 0;
        const __nv_bfloat16* a0h = Ahi + (size_t)gr0 * lda + kb + seg0 * 8;
        const __nv_bfloat16* a1h = Ahi + (size_t)gr1 * lda + kb + seg0 * 8;
        const __nv_bfloat16* a0l = Alo + (size_t)gr0 * lda + kb + seg0 * 8;
        const __nv_bfloat16* a1l = Alo + (size_t)gr1 * lda + kb + seg0 * 8;
        uint32_t d0 = base + r0i * 80 + seg0 * 16;
        uint32_t d1 = base + r1i * 80 + seg0 * 16;
        cp16(d0, a0h);          cp16(d1, a1h);
        cp16(d0 + 10240, a0l);  cp16(d1 + 10240, a1l);
        const __nv_bfloat16* b0h = Bhi + (size_t)(n0 + r0i) * K + kb + seg0 * 8;
        const __nv_bfloat16* b1h = Bhi + (size_t)(n0 + r1i) * K + kb + seg0 * 8;
        const __nv_bfloat16* b0l = Blo + (size_t)(n0 + r0i) * K + kb + seg0 * 8;
        const __nv_bfloat16* b1l = Blo + (size_t)(n0 + r1i) * K + kb + seg0 * 8;
        cp16(d0 + 20480, b0h);  cp16(d1 + 20480, b1h);
        cp16(d0 + 30720, b0l);  cp16(d1 + 30720, b1l);
    };

    float acc[4][4][4];
#pragma unroll
    for (int i = 0; i < 4; i++)
#pragma unroll
        for (int j = 0; j < 4; j++)
#pragma unroll
            for (int q = 0; q < 4; q++) acc[i][j][q] = 0.0f;

    load_stage(0, 0); CP_COMMIT();
    load_stage(1, 1); CP_COMMIT();

    int a_row = wm * 64 + (lane & 7) + ((lane >> 3) & 1) * 8;
    int a_colh = (lane >> 4) * 8;
    int b_row = wn * 32 + (lane & 7);
    int b_colh = ((lane >> 3) & 1) * 8;

    for (int ch = 0; ch < nch; ch++) {
        int st = ch % NSTG;
        CP_WAIT1();
        __syncthreads();
        if (ch + 2 < nch) load_stage((ch + 2) % NSTG, ch + 2);
        CP_COMMIT();
        uint32_t base = sb + st * STG_SZ;
#pragma unroll
        for (int k16 = 0; k16 < 2; k16++) {
            uint32_t ah[4][4], al[4][4], bh[4][2], bl[4][2];
#pragma unroll
            for (int mt = 0; mt < 4; mt++) {
                uint32_t ad = base + (a_row + mt * 16) * 80 + (k16 * 16 + a_colh) * 2;
                ldm_x4(ah[mt], ad);
                ldm_x4(al[mt], ad + 10240);
            }
#pragma unroll
            for (int nt = 0; nt < 4; nt++) {
                uint32_t bd = base + 20480 + (b_row + nt * 8) * 80 + (k16 * 16 + b_colh) * 2;
                ldm_x2(bh[nt], bd);
                ldm_x2(bl[nt], bd + 10240);
            }
#pragma unroll
            for (int mt = 0; mt < 4; mt++)
#pragma unroll
                for (int nt = 0; nt < 4; nt++) {
                    mma16816(acc[mt][nt], ah[mt], bh[nt]);
                    mma16816(acc[mt][nt], al[mt], bh[nt]);
                    mma16816(acc[mt][nt], ah[mt], bl[nt]);
                }
        }
    }

    // ------------- epilogue -------------
    float sum = 0.0f, ssum = 0.0f;
    int rbase = m0 + wm * 64 + (lane >> 2);
    int cbase = n0 + wn * 32 + (lane & 3) * 2;
#pragma unroll
    for (int mt = 0; mt < 4; mt++) {
#pragma unroll
        for (int half = 0; half < 2; half++) {
            int row = rbase + mt * 16 + half * 8;
            if (row >= NN) continue;
#pragma unroll
            for (int nt = 0; nt < 4; nt++) {
                int c = cbase + nt * 8;
                float v0 = acc[mt][nt][half * 2 + 0];
                float v1 = acc[mt][nt][half * 2 + 1];
                if (mode == 2) {
                    *(float2*)(g_h + (size_t)row * 256 + c) = make_float2(v0, v1);
                    sum += v0 + v1;
                    ssum += v0 * v0 + v1 * v1;
                } else if (mode == 1) {
                    float r0 = fmaxf(v0 + __ldg(&bias[c]), 0.0f);
                    float r1 = fmaxf(v1 + __ldg(&bias[c + 1]), 0.0f);
                    *(float2*)(g_x0 + (size_t)row * 256 + c) = make_float2(r0, r1);
                    __nv_bfloat16 h0, l0, h1, l1;
                    split2(0.5f * r0, h0, l0);
                    split2(0.5f * r1, h1, l1);
                    size_t sidx = (size_t)row * 512 + 256 + c;
                    *(__nv_bfloat162*)(g_A_hi + sidx) = __nv_bfloat162(h0, h1);
                    *(__nv_bfloat162*)(g_A_lo + sidx) = __nv_bfloat162(l0, l1);
                } else {
                    float r0 = fmaxf(v0 + __ldg(&bias[c]), 0.0f);
                    float r1 = fmaxf(v1 + __ldg(&bias[c + 1]), 0.0f);
                    *(float2*)(Cout + (size_t)row * N + c) = make_float2(r0, r1);
                }
            }
        }
    }
    if (mode == 2) {
#pragma unroll
        for (int off = 16; off > 0; off >>= 1) {
            sum  += __shfl_down_sync(0xffffffffu, sum, off);
            ssum += __shfl_down_sync(0xffffffffu, ssum, off);
        }
        __syncthreads();
        float* rs  = (float*)smem;
        float* rss = (float*)smem + 32;
        if (lane == 0) { rs[wrp] = sum; rss[wrp] = ssum; }
        __syncthreads();
        if (tid == 0) {
            float S = 0.f, SS = 0.f;
            for (int w = 0; w < 8; w++) { S += rs[w]; SS += rss[w]; }
            atomicAdd(&g_accA[parity][0], (double)S);
            atomicAdd(&g_accA[parity][1], (double)SS);
        }
    }
}

// ------------------------- final norm (fused stats) -> lin2 input splits --
__global__ void k_norm_final(const float* __restrict__ gam, const float* __restrict__ bet) {
    double cnt = (double)NN * (double)D_HID;
    double mu = g_accA[1][0] / cnt;
    double var = g_accA[1][1] / cnt - mu * mu;
    if (var < 0.0) var = 0.0;
    float inv = (float)(1.0 / (sqrt(var) + 1e-5));
    float muf = (float)mu;
    size_t total = (size_t)NN * D_HID / 4;
    size_t i = (size_t)blockIdx.x * blockDim.x + threadIdx.x;
    if (i >= total) return;
    float4 v = ((const float4*)g_h)[i];
    int c = (int)((i * 4) & (D_HID - 1));
    float4 gg = *(const float4*)(gam + c);
    float4 bb = *(const float4*)(bet + c);
    float r0 = fmaxf(gg.x * ((v.x - muf) * inv) + bb.x, 0.0f);
    float r1 = fmaxf(gg.y * ((v.y - muf) * inv) + bb.y, 0.0f);
    float r2 = fmaxf(gg.z * ((v.z - muf) * inv) + bb.z, 0.0f);
    float r3 = fmaxf(gg.w * ((v.w - muf) * inv) + bb.w, 0.0f);
    size_t row = (i * 4) >> 8;
    size_t base = row * 512 + c;
    __nv_bfloat16 h4[4], l4[4];
    split2(r0, h4[0], l4[0]); split2(r1, h4[1], l4[1]);
    split2(r2, h4[2], l4[2]); split2(r3, h4[3], l4[3]);
    *(__nv_bfloat162*)(g_A_hi + base)     = __nv_bfloat162(h4[0], h4[1]);
    *(__nv_bfloat162*)(g_A_hi + base + 2) = __nv_bfloat162(h4[2], h4[3]);
    *(__nv_bfloat162*)(g_A_lo + base)     = __nv_bfloat162(l4[0], l4[1]);
    *(__nv_bfloat162*)(g_A_lo + base + 2) = __nv_bfloat162(l4[2], l4[3]);
}

// ------------------------- launch -------------------------
extern "C" void kernel_launch(void* const* d_in, const int* in_sizes, int n_in,
                              void* d_out, int out_size) {
    const float* x       = (const float*)d_in[0];
    const int*   ei      = (const int*)  d_in[1];
    const float* lin1_w  = (const float*)d_in[2];
    const float* lin1_b  = (const float*)d_in[3];
    const float* conv_w1 = (const float*)d_in[4];
    const float* conv_w2 = (const float*)d_in[5];
    const float* gamma   = (const float*)d_in[6];
    const float* betaa   = (const float*)d_in[7];
    const float* lin2_w  = (const float*)d_in[8];
    const float* lin2_b  = (const float*)d_in[9];
    float* out = (float*)d_out;

    static int smem_set = 0;
    if (!smem_set) {
        cudaFuncSetAttribute(k_mma, cudaFuncAttributeMaxDynamicSharedMemorySize, SM_TOTAL);
        smem_set = 1;
    }

    // graph normalization + CSR build
    k_init<<<(NN + 255) / 256, 256>>>();
    k_edge_count<<<(NE + 255) / 256, 256>>>(ei);
    k_rsqrt<<<(NN + 255) / 256, 256>>>();
    k_scan_part<<<49, 1024>>>();
    k_scan_top<<<1, 64>>>();
    k_scan_out<<<49, 1024>>>();
    k_cursor<<<(NN + 255) / 256, 256>>>();
    k_scatter<<<(NE + 255) / 256, 256>>>(ei);

    // bf16 operand prep
    k_prep_w<<<(WB_TOT + 255) / 256, 256>>>(lin1_w, conv_w1, conv_w2, lin2_w);
    k_prep_x<<<(NN * D_IN + 255) / 256, 256>>>(x);

    const int MT = (NN + 127) / 128;  // 391

    // lin1 + relu -> g_x0 (+ 0.5*x0 splits)
    k_mma<<<dim3(2, MT), 256, SM_TOTAL>>>(1, WB_L1, 128, 256, lin1_b, nullptr, 0);

    // 8 GCNII layers: SpMM(fused prev-norm) + GEMM(W' pre-fused)
    for (int l = 0; l < NL; l++) {
        k_spmm<<<(NN + 7) / 8, 256>>>(l, gamma + (size_t)(l > 0 ? l - 1 : 0) * D_HID,
                                      betaa + (size_t)(l > 0 ? l - 1 : 0) * D_HID);
        k_mma<<<dim3(2, MT), 256, SM_TOTAL>>>(2, WB_LYR + l * 131072, 512, 256,
                                              nullptr, nullptr, l & 1);
    }

    // final norm (layer 7 params) -> lin2 input splits
    k_norm_final<<<(NN * D_HID / 4 + 255) / 256, 256>>>(gamma + 7 * (size_t)D_HID,
                                                        betaa + 7 * (size_t)D_HID);

    // lin2 + relu -> out
    k_mma<<<dim3(1, MT), 256, SM_TOTAL>>>(3, WB_L2, 256, 128, lin2_b, out, 0);

    (void)in_sizes; (void)n_in; (void)out_size;
}